// round 14
// baseline (speedup 1.0000x reference)
#include <cuda_runtime.h>
#include <cstdint>
#include <math.h>

// Problem constants
#define BATCH   32
#define SEQT    512
#define DIN     512
#define HID     512
#define LAYERS  2
#define G4      (4*HID)

// Persistent-kernel config
#define NCTA    128              // 64 CTAs per layer
#define CPL     64
#define THREADS 512              // 16 warps = 2 j-quads x 8 k-groups
#define JPC     8

// SMEM float offsets
#define OFF_WX   0                        // [32 rows][512]
#define OFF_WH   16384
#define OFF_BUF  32768                    // 2 bufs x 8192 floats (in0 4096 | in1 4096)
#define OFF_RED  OFF_BUF                  // 8192 floats, aliases buf0 post-compute
#define OFF_BIAS (OFF_BUF + 16384)        // 49152
#define OFF_MBAR (OFF_BIAS + 32)          // 49184 (byte 196736, 8B aligned)
#define SMEM_FLOATS (OFF_MBAR + 4)
#define SMEM_BYTES  (SMEM_FLOATS * 4)

// ---------------- device scratch -------------------------------------------
// PACKED layouts: element (k,b) lives at (k>>1)*64 + b*2 + (k&1)  [floats]
__device__ float    g_xT[SEQT * DIN * BATCH];      // [t][kp][b][2]
__device__ float    g_h[LAYERS][2][HID * BATCH];   // [l][par][jp][b][2]
__device__ unsigned g_arr[2];
__device__ unsigned g_rel[2];

// ---------------- transpose x + barrier reset (one launch) ------------------
__global__ void transpose_x_kernel(const float* __restrict__ x) {
    if (blockIdx.x == 0 && blockIdx.y == 0 &&
        threadIdx.x == 0 && threadIdx.y == 0) {
        g_arr[0] = 0u; g_arr[1] = 0u;
        g_rel[0] = 0u; g_rel[1] = 0u;
    }
    __shared__ float tile[32][33];
    int t  = blockIdx.x;
    int k0 = blockIdx.y * 32;
    int lx = threadIdx.x;
    for (int bb = threadIdx.y; bb < 32; bb += 8)
        tile[bb][lx] = x[((bb * SEQT + t) * DIN) + k0 + lx];
    __syncthreads();
    for (int kk = threadIdx.y; kk < 32; kk += 8) {
        int k = k0 + kk;
        g_xT[t * 16384 + (k >> 1) * 64 + lx * 2 + (k & 1)] = tile[lx][kk];
    }
}

// ---------------- helpers ----------------------------------------------------
__device__ __forceinline__ uint32_t smem_u32(const void* p) {
    uint32_t a;
    asm("{ .reg .u64 t; cvta.to.shared.u64 t, %1; cvt.u32.u64 %0, t; }"
        : "=r"(a) : "l"(p));
    return a;
}

// "memory" clobber is load-bearing (R8 bug).
__device__ __forceinline__ unsigned ld_rel(const unsigned* p) {
    unsigned v;
    asm volatile("ld.global.cg.u32 %0, [%1];" : "=r"(v) : "l"(p) : "memory");
    return v;
}
__device__ __forceinline__ void spin_until(const unsigned* p, unsigned need) {
    while (ld_rel(p) < need) { __nanosleep(64); }
}

__device__ __forceinline__ void layer_barrier(int l, unsigned gen) {
    __threadfence();
    __syncthreads();
    if (threadIdx.x == 0) {
        unsigned a = atomicAdd(&g_arr[l], 1u);
        if (a + 1u == gen * (unsigned)CPL) {
            atomicExch(&g_rel[l], gen);
        } else {
            spin_until(&g_rel[l], gen);
        }
        __threadfence();
    }
    __syncthreads();
}

__device__ __forceinline__ float sigmoidf_(float v) {
    return 1.0f / (1.0f + expf(-v));
}

__device__ __forceinline__ void fma2(unsigned long long& d,
                                     unsigned long long a,
                                     unsigned long long b) {
    asm("fma.rn.f32x2 %0, %1, %2, %0;" : "+l"(d) : "l"(a), "l"(b));
}
__device__ __forceinline__ float2 u2f2(unsigned long long v) {
    float2 f;
    asm("mov.b64 {%0, %1}, %2;" : "=f"(f.x), "=f"(f.y) : "l"(v));
    return f;
}
struct ull2 { unsigned long long x, y; };

// ---- TMA bulk staging ----
__device__ __forceinline__ void mbar_init(uint32_t mbar) {
    asm volatile("mbarrier.init.shared.b64 [%0], 1;" :: "r"(mbar) : "memory");
}
__device__ __forceinline__ void tma_issue(uint32_t dst,
                                          const float* s0, const float* s1,
                                          uint32_t mbar) {
    asm volatile("mbarrier.arrive.expect_tx.shared::cta.b64 _, [%0], %1;"
                 :: "r"(mbar), "r"(32768u) : "memory");
    asm volatile("cp.async.bulk.shared::cta.global.mbarrier::complete_tx::bytes "
                 "[%0], [%1], %2, [%3];"
                 :: "r"(dst), "l"(s0), "r"(16384u), "r"(mbar) : "memory");
    asm volatile("cp.async.bulk.shared::cta.global.mbarrier::complete_tx::bytes "
                 "[%0], [%1], %2, [%3];"
                 :: "r"(dst + 16384u), "l"(s1), "r"(16384u), "r"(mbar) : "memory");
}
__device__ __forceinline__ void mbar_wait(uint32_t mbar, uint32_t parity) {
    asm volatile(
        "{\n\t.reg .pred P;\n\t"
        "W%=:\n\t"
        "mbarrier.try_wait.parity.acquire.cta.shared::cta.b64 P, [%0], %1, 0x989680;\n\t"
        "@P bra D%=;\n\t"
        "bra W%=;\n\t"
        "D%=:\n\t}"
        :: "r"(mbar), "r"(parity) : "memory");
}

// One 16-k slice for warp (d = j-quad, q = k-group), round r.
// acc[j*4+g] accumulates Wx and Wh contributions together.
__device__ __forceinline__ void compute_round(const float* smem, int r,
                                              int d, int q, int lane,
                                              unsigned long long* acc) {
    const unsigned long long* in0p =
        (const unsigned long long*)(smem + OFF_BUF + (r & 1) * 8192);
    const unsigned long long* in1p = in0p + 2048;
    const int base = q * 8;                 // local kp start
    const int kw0  = r * 128 + q * 16;      // absolute k for weights
    #pragma unroll
    for (int i = 0; i < 4; ++i) {
        const int pi = base + 2 * i;
        unsigned long long p00 = in0p[(pi + 0) * 32 + lane];
        unsigned long long p01 = in0p[(pi + 1) * 32 + lane];
        unsigned long long p10 = in1p[(pi + 0) * 32 + lane];
        unsigned long long p11 = in1p[(pi + 1) * 32 + lane];
        const int kw = kw0 + 4 * i;
        #pragma unroll
        for (int j = 0; j < 4; ++j) {
            #pragma unroll
            for (int g = 0; g < 4; ++g) {
                const int row = ((d * 4 + j) * 4 + g) << 9;
                ull2 wx = *(const ull2*)&smem[OFF_WX + row + kw];
                ull2 wh = *(const ull2*)&smem[OFF_WH + row + kw];
                unsigned long long& a = acc[j * 4 + g];
                fma2(a, wx.x, p00);
                fma2(a, wx.y, p01);
                fma2(a, wh.x, p10);
                fma2(a, wh.y, p11);
            }
        }
    }
}

// ---------------- persistent LSTM kernel ------------------------------------
__global__ void __launch_bounds__(THREADS, 1)
lstm_persist(const float* __restrict__ h0,
             const float* __restrict__ c0,
             const float* __restrict__ Wx,   // [L][4H][D]
             const float* __restrict__ bx,
             const float* __restrict__ Wh,   // [L][4H][H]
             const float* __restrict__ bh,
             float* __restrict__ out,
             int out_size) {
    extern __shared__ float smem[];
    float* s_bias = smem + OFF_BIAS;
    const uint32_t mb0 = smem_u32(smem + OFF_MBAR);
    const uint32_t mb1 = mb0 + 8;
    const uint32_t buf0 = smem_u32(smem + OFF_BUF);
    const uint32_t buf1 = buf0 + 32768u;

    const int cta   = blockIdx.x;
    const int l     = cta >> 6;
    const int jbase = (cta & 63) * JPC;
    const int tid   = threadIdx.x;
    const int w     = tid >> 5;
    const int lane  = tid & 31;              // batch
    const int d_    = w >> 3;                // j-quad: j in [4d, 4d+4)
    const int q_    = w & 7;                 // k-group 0..7 (16k per round)
    const bool owner = (w < 8);              // owner w handles jl = w
    const int  jl    = w & 7;
    const int  j     = jbase + jl;

    if (tid == 0) {
        mbar_init(mb0);
        mbar_init(mb1);
        asm volatile("fence.proxy.async.shared::cta;" ::: "memory");
    }

    // ---- load this CTA's weight rows into SMEM (once) ----
    for (int i = tid * 4; i < 32 * 512; i += THREADS * 4) {
        int row  = i >> 9;                   // j_local*4 + gate
        int k    = i & 511;
        int grow = l * G4 + (row & 3) * HID + jbase + (row >> 2);
        *(float4*)&smem[OFF_WX + i] = *(const float4*)&Wx[(size_t)grow * DIN + k];
        *(float4*)&smem[OFF_WH + i] = *(const float4*)&Wh[(size_t)grow * HID + k];
    }
    if (tid < 32) {
        int grow = l * G4 + (tid & 3) * HID + jbase + (tid >> 2);
        s_bias[tid] = bx[grow] + bh[grow];   // s_bias[j*4+g]
    }

    // ---- init state (owners hold c/h for their j) ----
    float c_reg  = c0[(lane * LAYERS + l) * HID + j];
    float h_last = h0[(lane * LAYERS + l) * HID + j];
    const int hpix = ((j >> 1) * 32 + lane) * 2 + (j & 1);   // packed h index
    if (owner) {
        __stcg(&g_h[l][0][hpix], h_last);    // both parities (replay safety)
        __stcg(&g_h[l][1][hpix], h_last);
    }

    layer_barrier(l, 1u);    // also orders mbar_init before any TMA use

    unsigned cnt0 = 0, cnt1 = 0;             // mbar phase counters

    for (int t = 0; t < SEQT; ++t) {
        if (l == 1) {
            spin_until(&g_rel[0], (unsigned)(t + 2));  // RAW: layer-0 step t done
            __syncthreads();
        }
        const float* src0 = (l == 0) ? (g_xT + (size_t)t * 16384)
                                     : &g_h[0][t & 1][0];
        const float* src1 = &g_h[l][(t + 1) & 1][0];

        unsigned long long acc[16];
        #pragma unroll
        for (int g = 0; g < 16; ++g) acc[g] = 0ull;

        // issue round 0 (buf0 free: previous phase ended with layer_barrier)
        if (tid == 0) tma_issue(buf0, src0, src1, mb0);

        #pragma unroll 1
        for (int r = 0; r < 4; ++r) {
            __syncthreads();   // all warps done with compute r-1 -> buf[(r+1)&1] free
            if (r < 3 && tid == 0) {
                const int rn = r + 1;
                tma_issue((rn & 1) ? buf1 : buf0,
                          src0 + rn * 4096, src1 + rn * 4096,
                          (rn & 1) ? mb1 : mb0);
            }
            if (r & 1) { mbar_wait(mb1, cnt1 & 1); cnt1++; }
            else       { mbar_wait(mb0, cnt0 & 1); cnt0++; }
            compute_round(smem, r, d_, q_, lane, acc);
        }
        __syncthreads();       // compute done; buf0 reusable as reduction array

        // ---- publish k-group partials: red[(row*8+q)*32+lane] ----
        #pragma unroll
        for (int idx = 0; idx < 16; ++idx) {
            const int jj = idx >> 2, g = idx & 3;
            const int row = (d_ * 4 + jj) * 4 + g;
            float2 v = u2f2(acc[idx]);
            smem[OFF_RED + (row * 8 + q_) * 32 + lane] = v.x + v.y;
        }
        // layer-0 WAR clearance (overlapped with publish; sync follows)
        if (l == 0 && tid == 0 && t >= 2) {
            spin_until(&g_rel[1], (unsigned)t);
        }
        __syncthreads();

        if (owner) {
            float pre[4];
            #pragma unroll
            for (int g = 0; g < 4; ++g) {
                const float* rp = &smem[OFF_RED + ((jl * 4 + g) * 8) * 32 + lane];
                float s = ((rp[0] + rp[32]) + (rp[64] + rp[96]))
                        + ((rp[128] + rp[160]) + (rp[192] + rp[224]));
                pre[g] = s + s_bias[(jl << 2) | g];
            }
            float ig = sigmoidf_(pre[0]);
            float fg = sigmoidf_(pre[1]);
            float gg = tanhf(pre[2]);
            float og = sigmoidf_(pre[3]);

            c_reg  = fg * c_reg + ig * gg;
            float hN = og * tanhf(c_reg);
            h_last = hN;

            __stcg(&g_h[l][t & 1][hpix], hN);
            if (l == 1)
                out[((size_t)lane * SEQT + t) * HID + j] = hN;
        }

        layer_barrier(l, (unsigned)(t + 2));
    }

    // ---- final h_n / c_n: [L][B][H] each, appended after output ----
    if (owner &&
        out_size >= BATCH * SEQT * HID + 2 * LAYERS * BATCH * HID) {
        float* hn = out + (size_t)BATCH * SEQT * HID;
        float* cn = hn + (size_t)LAYERS * BATCH * HID;
        hn[((size_t)l * BATCH + lane) * HID + j] = h_last;
        cn[((size_t)l * BATCH + lane) * HID + j] = c_reg;
    }
}

// ---------------- launch -----------------------------------------------------
extern "C" void kernel_launch(void* const* d_in, const int* in_sizes, int n_in,
                              void* d_out, int out_size) {
    const float* x  = (const float*)d_in[0];
    const float* h0 = (const float*)d_in[1];
    const float* c0 = (const float*)d_in[2];
    const float* Wx = (const float*)d_in[3];
    const float* bx = (const float*)d_in[4];
    const float* Wh = (const float*)d_in[5];
    const float* bh = (const float*)d_in[6];
    float* out = (float*)d_out;
    (void)in_sizes; (void)n_in;

    cudaFuncSetAttribute(lstm_persist,
                         cudaFuncAttributeMaxDynamicSharedMemorySize, SMEM_BYTES);

    dim3 tb(32, 8);
    dim3 tg(SEQT, DIN / 32);
    transpose_x_kernel<<<tg, tb>>>(x);   // also resets barrier state

    lstm_persist<<<NCTA, THREADS, SMEM_BYTES>>>(h0, c0, Wx, bx, Wh, bh, out, out_size);
}

// round 16
// speedup vs baseline: 1.4560x; 1.4560x over previous
#include <cuda_runtime.h>
#include <cstdint>
#include <math.h>

// Problem constants
#define BATCH   32
#define SEQT    512
#define DIN     512
#define HID     512
#define LAYERS  2
#define G4      (4*HID)

// Persistent-kernel config
#define NCTA    128              // 64 CTAs per layer
#define CPL     64
#define THREADS 512              // 16 warps = 2 j-quads x 8 k-groups
#define JPC     8

// SMEM float offsets
#define OFF_WX   0                       // [32 rows][512]
#define OFF_WH   16384
#define OFF_BUF  32768                   // 4 bufs x 4096 floats (packed pairs)
#define OFF_RED  OFF_BUF                 // 8192 floats, aliases bufs post-compute
#define OFF_BIAS (OFF_BUF + 16384)
#define SMEM_FLOATS (OFF_BIAS + 32)
#define SMEM_BYTES  (SMEM_FLOATS * 4)    // ~196.7 KB

// ---------------- device scratch -------------------------------------------
__device__ float    g_xT[SEQT * DIN * BATCH];      // x transposed: [t][k][b]
__device__ float    g_h[LAYERS][2][HID * BATCH];   // ping-pong h per layer
__device__ unsigned g_arr[2];
__device__ unsigned g_rel[2];

// ---------------- transpose x + barrier reset (one launch) ------------------
__global__ void transpose_x_kernel(const float* __restrict__ x) {
    if (blockIdx.x == 0 && blockIdx.y == 0 &&
        threadIdx.x == 0 && threadIdx.y == 0) {
        g_arr[0] = 0u; g_arr[1] = 0u;
        g_rel[0] = 0u; g_rel[1] = 0u;
    }
    __shared__ float tile[32][33];
    int t  = blockIdx.x;
    int k0 = blockIdx.y * 32;
    int lx = threadIdx.x;
    for (int bb = threadIdx.y; bb < 32; bb += 8)
        tile[bb][lx] = x[((bb * SEQT + t) * DIN) + k0 + lx];
    __syncthreads();
    for (int kk = threadIdx.y; kk < 32; kk += 8)
        g_xT[(t * DIN + (k0 + kk)) * BATCH + lx] = tile[lx][kk];
}

// ---------------- helpers ----------------------------------------------------
// "memory" clobber is load-bearing (R8 bug: hoisted data loads past spin).
__device__ __forceinline__ unsigned ld_rel(const unsigned* p) {
    unsigned v;
    asm volatile("ld.global.cg.u32 %0, [%1];" : "=r"(v) : "l"(p) : "memory");
    return v;
}
__device__ __forceinline__ void spin_until(const unsigned* p, unsigned need) {
    while (ld_rel(p) < need) { __nanosleep(64); }
}

// per-layer 64-CTA barrier, cumulative generation
__device__ __forceinline__ void layer_barrier(int l, unsigned gen) {
    __threadfence();
    __syncthreads();
    if (threadIdx.x == 0) {
        unsigned a = atomicAdd(&g_arr[l], 1u);
        if (a + 1u == gen * (unsigned)CPL) {
            atomicExch(&g_rel[l], gen);
        } else {
            spin_until(&g_rel[l], gen);
        }
        __threadfence();
    }
    __syncthreads();
}

__device__ __forceinline__ float sigmoidf_(float v) {
    return 1.0f / (1.0f + expf(-v));
}

// packed f32x2 FMA: d = a*b + d
__device__ __forceinline__ void fma2(unsigned long long& d,
                                     unsigned long long a,
                                     unsigned long long b) {
    asm("fma.rn.f32x2 %0, %1, %2, %0;" : "+l"(d) : "l"(a), "l"(b));
}
__device__ __forceinline__ float2 u2f2(unsigned long long v) {
    float2 f;
    asm("mov.b64 {%0, %1}, %2;" : "=f"(f.x), "=f"(f.y) : "l"(v));
    return f;
}
struct ull2 { unsigned long long x, y; };

// One 32-k slice for warp (d = j-quad, q = k-group 0..7), round r (256 k).
// acc[j*4+g] accumulates Wx and Wh contributions together (J=4 tiling:
// each act pair feeds 16 FMA2 -> act LDS halved vs J=2).
__device__ __forceinline__ void compute_round(const float* smem, int r,
                                              int d, int q, int lane,
                                              unsigned long long* acc) {
    const unsigned long long* in0p =
        (const unsigned long long*)(smem + OFF_BUF + ((q >> 2) << 1) * 4096);
    const unsigned long long* in1p = in0p + 2048;   // next buf
    const int po  = (q & 3) << 4;                   // pair offset 0,16,32,48
    const int kw0 = r * 256 + (q >> 2) * 128 + (q & 3) * 32;
    #pragma unroll 2
    for (int i = 0; i < 8; ++i) {
        const int pi = po + 2 * i;
        unsigned long long p00 = in0p[(pi + 0) * 32 + lane];
        unsigned long long p01 = in0p[(pi + 1) * 32 + lane];
        unsigned long long p10 = in1p[(pi + 0) * 32 + lane];
        unsigned long long p11 = in1p[(pi + 1) * 32 + lane];
        const int kw = kw0 + 4 * i;
        #pragma unroll
        for (int j = 0; j < 4; ++j) {
            #pragma unroll
            for (int g = 0; g < 4; ++g) {
                const int row = ((d * 4 + j) * 4 + g) << 9;
                ull2 wx = *(const ull2*)&smem[OFF_WX + row + kw];
                ull2 wh = *(const ull2*)&smem[OFF_WH + row + kw];
                unsigned long long& a = acc[j * 4 + g];
                fma2(a, wx.x, p00);
                fma2(a, wx.y, p01);
                fma2(a, wh.x, p10);
                fma2(a, wh.y, p11);
            }
        }
    }
}

// ---------------- persistent LSTM kernel ------------------------------------
__global__ void __launch_bounds__(THREADS, 1)
lstm_persist(const float* __restrict__ h0,
             const float* __restrict__ c0,
             const float* __restrict__ Wx,   // [L][4H][D]
             const float* __restrict__ bx,
             const float* __restrict__ Wh,   // [L][4H][H]
             const float* __restrict__ bh,
             float* __restrict__ out,
             int out_size) {
    extern __shared__ float smem[];
    float* s_bias = smem + OFF_BIAS;

    const int cta   = blockIdx.x;
    const int l     = cta >> 6;              // layer 0/1
    const int jbase = (cta & 63) * JPC;
    const int tid   = threadIdx.x;
    const int w     = tid >> 5;              // 0..15
    const int lane  = tid & 31;              // batch index
    const int d_    = w >> 3;                // j-quad: j in [4d, 4d+4)
    const int q_    = w & 7;                 // k-group 0..7 (32k per round)
    const bool owner = (w < 8);              // owner w finalizes jl = w
    const int  jl    = w & 7;
    const int  j     = jbase + jl;

    // ---- load this CTA's weight rows into SMEM (once) ----
    for (int i = tid * 4; i < 32 * 512; i += THREADS * 4) {
        int row  = i >> 9;                   // j_local*4 + gate
        int k    = i & 511;
        int grow = l * G4 + (row & 3) * HID + jbase + (row >> 2);
        *(float4*)&smem[OFF_WX + i] = *(const float4*)&Wx[(size_t)grow * DIN + k];
        *(float4*)&smem[OFF_WH + i] = *(const float4*)&Wh[(size_t)grow * HID + k];
    }
    if (tid < 32) {
        int grow = l * G4 + (tid & 3) * HID + jbase + (tid >> 2);
        s_bias[tid] = bx[grow] + bh[grow];   // s_bias[j*4 + g]
    }

    // ---- init state (owners hold c/h for their j) ----
    float c_reg  = c0[(lane * LAYERS + l) * HID + j];
    float h_last = h0[(lane * LAYERS + l) * HID + j];
    if (owner) {
        // both parities: g_h persists across graph replays
        __stcg(&g_h[l][0][j * BATCH + lane], h_last);
        __stcg(&g_h[l][1][j * BATCH + lane], h_last);
    }

    layer_barrier(l, 1u);

    // staging geometry: thread handles pair-index kp, batch group bg, 4 bufs
    const int kp = tid >> 3;                 // 0..63
    const int bg = (tid & 7) << 2;           // 0,4,...,28

    // ---- per-layer step loop (layer-1 trails via RAW wait; 2-step slack) ----
    for (int t = 0; t < SEQT; ++t) {
        if (l == 1) {
            spin_until(&g_rel[0], (unsigned)(t + 2));  // RAW: layer-0 step t done
            __syncthreads();   // no data load may precede the spin
        }
        const float* in0 = (l == 0) ? &g_xT[(size_t)t * DIN * BATCH]
                                    : &g_h[0][t & 1][0];
        const float* in1 = &g_h[l][(t + 1) & 1][0];

        unsigned long long acc[16];
        #pragma unroll
        for (int g = 0; g < 16; ++g) acc[g] = 0ull;

        float4 f[8];
        // ---- load + store round 0: bufs {0,1}=k[0,128), {2,3}=[128,256)
        #pragma unroll
        for (int b = 0; b < 4; ++b) {
            const float* src = ((b & 1) ? in1 : in0)
                             + (((b >> 1) ? 128 : 0) + 2 * kp) * BATCH + bg;
            f[2 * b]     = __ldcg((const float4*)src);
            f[2 * b + 1] = __ldcg((const float4*)(src + BATCH));
        }
        #pragma unroll
        for (int b = 0; b < 4; ++b) {
            float4 fa = f[2 * b], fb = f[2 * b + 1];
            float* dst = smem + OFF_BUF + b * 4096 + (kp * 32 + bg) * 2;
            *(float4*)(dst)     = make_float4(fa.x, fb.x, fa.y, fb.y);
            *(float4*)(dst + 4) = make_float4(fa.z, fb.z, fa.w, fb.w);
        }
        __syncthreads();

        // ---- issue round-1 loads (hidden under round-0 compute) ----
        #pragma unroll
        for (int b = 0; b < 4; ++b) {
            const float* src = ((b & 1) ? in1 : in0)
                             + (256 + ((b >> 1) ? 128 : 0) + 2 * kp) * BATCH + bg;
            f[2 * b]     = __ldcg((const float4*)src);
            f[2 * b + 1] = __ldcg((const float4*)(src + BATCH));
        }

        compute_round(smem, 0, d_, q_, lane, acc);
        __syncthreads();

        #pragma unroll
        for (int b = 0; b < 4; ++b) {
            float4 fa = f[2 * b], fb = f[2 * b + 1];
            float* dst = smem + OFF_BUF + b * 4096 + (kp * 32 + bg) * 2;
            *(float4*)(dst)     = make_float4(fa.x, fb.x, fa.y, fb.y);
            *(float4*)(dst + 4) = make_float4(fa.z, fb.z, fa.w, fb.w);
        }
        __syncthreads();

        compute_round(smem, 1, d_, q_, lane, acc);
        __syncthreads();      // bufs free before red aliases onto them

        // ---- publish k-group partials: red[(row*8+q)*32+lane] ----
        #pragma unroll
        for (int idx = 0; idx < 16; ++idx) {
            const int jj = idx >> 2, g = idx & 3;
            const int row = (d_ * 4 + jj) * 4 + g;
            float2 v = u2f2(acc[idx]);
            smem[OFF_RED + (row * 8 + q_) * 32 + lane] = v.x + v.y;
        }
        // layer-0 WAR clearance (overlapped with publish; sync follows)
        if (l == 0 && tid == 0 && t >= 2) {
            spin_until(&g_rel[1], (unsigned)t);
        }
        __syncthreads();

        if (owner) {
            float pre[4];
            #pragma unroll
            for (int g = 0; g < 4; ++g) {
                const float* rp = &smem[OFF_RED + ((jl * 4 + g) * 8) * 32 + lane];
                float s = ((rp[0] + rp[32]) + (rp[64] + rp[96]))
                        + ((rp[128] + rp[160]) + (rp[192] + rp[224]));
                pre[g] = s + s_bias[(jl << 2) | g];
            }
            float ig = sigmoidf_(pre[0]);
            float fg = sigmoidf_(pre[1]);
            float gg = tanhf(pre[2]);
            float og = sigmoidf_(pre[3]);

            c_reg  = fg * c_reg + ig * gg;
            float hN = og * tanhf(c_reg);
            h_last = hN;

            __stcg(&g_h[l][t & 1][j * BATCH + lane], hN);
            if (l == 1)
                out[((size_t)lane * SEQT + t) * HID + j] = hN;
        }

        layer_barrier(l, (unsigned)(t + 2));
    }

    // ---- final h_n / c_n: [L][B][H] each, appended after output ----
    if (owner &&
        out_size >= BATCH * SEQT * HID + 2 * LAYERS * BATCH * HID) {
        float* hn = out + (size_t)BATCH * SEQT * HID;
        float* cn = hn + (size_t)LAYERS * BATCH * HID;
        hn[((size_t)l * BATCH + lane) * HID + j] = h_last;
        cn[((size_t)l * BATCH + lane) * HID + j] = c_reg;
    }
}

// ---------------- launch -----------------------------------------------------
extern "C" void kernel_launch(void* const* d_in, const int* in_sizes, int n_in,
                              void* d_out, int out_size) {
    const float* x  = (const float*)d_in[0];
    const float* h0 = (const float*)d_in[1];
    const float* c0 = (const float*)d_in[2];
    const float* Wx = (const float*)d_in[3];
    const float* bx = (const float*)d_in[4];
    const float* Wh = (const float*)d_in[5];
    const float* bh = (const float*)d_in[6];
    float* out = (float*)d_out;
    (void)in_sizes; (void)n_in;

    cudaFuncSetAttribute(lstm_persist,
                         cudaFuncAttributeMaxDynamicSharedMemorySize, SMEM_BYTES);

    dim3 tb(32, 8);
    dim3 tg(SEQT, DIN / 32);
    transpose_x_kernel<<<tg, tb>>>(x);   // also resets barrier state

    lstm_persist<<<NCTA, THREADS, SMEM_BYTES>>>(h0, c0, Wx, bx, Wh, bh, out, out_size);
}